// round 14
// baseline (speedup 1.0000x reference)
#include <cuda_runtime.h>
#include <cuda_bf16.h>
#include <math.h>
#include <stdint.h>

#define L_    13
#define B_    16
#define S_    512
#define H_    768
#define QL    20
#define DL    492
#define NB    11
#define HID   5
#define NALL  14
#define KC    64            // K floats per chunk (256B/row fp32)
#define NCH   12            // 768 / 64
#define NDCH  4
#define EPSF  1e-8f
#define THR   256
#define NWORK (L_ * B_ * NDCH)   // 832 tiles
#define NWKR  296                // persistent workers = 2 per SM

__device__ int g_hist[NWORK * NB];
__device__ int g_arrive = 0;

// dynamic smem: 2 stages of raw fp32 (Q 20x256B @0, D 128x256B @5120)
#define STAGE 37888
#define SM_DN 75776          // 128 floats
#define SM_QN 76288          // 20 floats
#define SM_HI 76368          // 11 ints
#define SM_SZ 76416

extern __shared__ char smdyn[];

// 32B-granule XOR swizzle within a 256B row
__device__ __forceinline__ int swr(int row) { return (row & 7) ^ ((row >> 3) & 1); }
__device__ __forceinline__ uint32_t soff(int row, int col) {
    return (uint32_t)(row * 256 + ((((col >> 5) ^ swr(row)) << 5) | (col & 31)));
}

__device__ __forceinline__ uint32_t bfpack(float lo, float hi) {
    uint32_t r;
    asm("cvt.rn.bf16x2.f32 %0, %1, %2;" : "=r"(r) : "f"(hi), "f"(lo));
    return r;
}
__device__ __forceinline__ void cp16(void* dst, const void* src, bool pred) {
    unsigned s = (unsigned)__cvta_generic_to_shared(dst);
    int n = pred ? 16 : 0;
    asm volatile("cp.async.cg.shared.global [%0], [%1], 16, %2;"
                 :: "r"(s), "l"(src), "r"(n));
}
__device__ __forceinline__ void cp_commit() {
    asm volatile("cp.async.commit_group;");
}
template <int N>
__device__ __forceinline__ void cp_wait() {
    asm volatile("cp.async.wait_group %0;" :: "n"(N));
}
__device__ __forceinline__ void mma16816(float* c, uint32_t a0, uint32_t a1,
                                         uint32_t a2, uint32_t a3,
                                         uint32_t b0, uint32_t b1) {
    asm volatile(
        "mma.sync.aligned.m16n8k16.row.col.f32.bf16.bf16.f32 "
        "{%0,%1,%2,%3}, {%4,%5,%6,%7}, {%8,%9}, {%0,%1,%2,%3};"
        : "+f"(c[0]), "+f"(c[1]), "+f"(c[2]), "+f"(c[3])
        : "r"(a0), "r"(a1), "r"(a2), "r"(a3), "r"(b0), "r"(b1));
}

__global__ __launch_bounds__(THR)
void cedr_fused_kernel(const float* __restrict__ hs,
                       const float* __restrict__ W_hist,
                       const float* __restrict__ b_hist,
                       const float* __restrict__ W_comb,
                       const float* __restrict__ b_comb,
                       float* __restrict__ out) {
    const int tid  = threadIdx.x;
    const int lane = tid & 31;
    const int wid  = tid >> 5;

    // ======================= FINALIZER CTA (scheduled last) =======================
    if (blockIdx.x == NWKR) {
        if (tid == 0) {
            while (atomicCAS(&g_arrive, NWORK, 0) != NWORK) {}
            __threadfence();
        }
        __syncthreads();
        const float inv_n = 1.0f / (float)(QL * DL);
        for (int b = wid; b < B_; b += 8) {
            float sum = 0.f;
            const float* cls = hs + (size_t)(12 * B_ + b) * S_ * H_;
            for (int h = lane; h < H_; h += 32) sum += cls[h] * W_comb[h];
            for (int i = lane; i < NALL * NB; i += 32) {
                int lp = i / NB, n = i % NB;
                int lsrc = (lp == 0) ? 0 : lp - 1;
                int cnt = 0;
                #pragma unroll
                for (int d = 0; d < NDCH; d++)
                    cnt += g_hist[(((lsrc * B_ + b) << 2) + d) * NB + n];
                float coef = 0.f;
                #pragma unroll
                for (int o = 0; o < HID; o++)
                    coef += W_hist[o * NB + n] * W_comb[H_ + lp * HID + o];
                sum += (float)cnt * inv_n * coef;
            }
            if (lane == 0) {
                float cst = b_comb[0];
                for (int lp = 0; lp < NALL; lp++)
                    #pragma unroll
                    for (int o = 0; o < HID; o++)
                        cst += b_hist[o] * W_comb[H_ + lp * HID + o];
                sum += cst;
            }
            #pragma unroll
            for (int o = 16; o > 0; o >>= 1)
                sum += __shfl_xor_sync(0xffffffffu, sum, o);
            if (lane == 0) out[b] = sum;
        }
        return;
    }

    // ======================= PERSISTENT WORKER CTA =======================
    const int w = blockIdx.x;                      // 0..295
    const int ntiles = (NWORK - w + NWKR - 1) / NWKR;   // 3 for w<240 else 2
    const int total_ch = ntiles * NCH;

    float* sDn = reinterpret_cast<float*>(smdyn + SM_DN);
    float* sQn = reinterpret_cast<float*>(smdyn + SM_QN);
    int*   sHist = reinterpret_cast<int*>(smdyn + SM_HI);

    // staging roles (identical to R9 champion)
    const int c16 = lane & 15;
    const int lane_hi = lane >> 4;
    const int rbase = wid * 16 + lane_hi * 8;

    // issue chunk by GLOBAL chunk index (pipeline never drains across tiles)
    auto issue_gc = [&](int gc) {
        const int t  = gc / NCH;
        const int c  = gc - t * NCH;
        const int s  = gc & 1;
        const int idt = w + NWKR * t;              // tile id 0..831
        const int dcc = idt & 3, bb = (idt >> 2) & 15, ll = idt >> 6;
        const float* qb = hs + (size_t)(ll * B_ + bb) * S_ * H_;
        const float* db = qb + (size_t)QL * H_;
        char* stA = smdyn + s * STAGE;
        char* stB = stA + 5120;
        #pragma unroll
        for (int j = 0; j < 8; j++) {
            int row = rbase + j;
            int dgl = dcc * 128 + row;
            cp16(stB + soff(row, c16 * 16),
                 db + (size_t)dgl * H_ + c * KC + c16 * 4, dgl < DL);
        }
        {   // Q rows 0..15
            int qr = tid >> 4, qc = tid & 15;
            cp16(stA + soff(qr, qc * 16),
                 qb + (size_t)qr * H_ + c * KC + qc * 4, true);
        }
        if (tid < 64) {  // Q rows 16..19
            int qr = 16 + (tid >> 4), qc = tid & 15;
            cp16(stA + soff(qr, qc * 16),
                 qb + (size_t)qr * H_ + c * KC + qc * 4, true);
        }
        cp_commit();
    };

    // MMA fragment geometry (identical)
    const int g = lane >> 2, tig = lane & 3;
    const int mi = wid & 1;
    const int n0 = (wid >> 1) * 32;
    const int ar0 = 16 * mi + g, ar1 = ar0 + 8;

    issue_gc(0);
    issue_gc(1);

    #pragma unroll 1
    for (int t = 0; t < ntiles; t++) {
        const int idt = w + NWKR * t;
        const int dstart = (idt & 3) * 128;

        float acc[4][4];
        #pragma unroll
        for (int j = 0; j < 4; j++)
            #pragma unroll
            for (int k = 0; k < 4; k++) acc[j][k] = 0.f;
        float dn2[4] = {0.f, 0.f, 0.f, 0.f};
        float qn2a = 0.f, qn2b = 0.f;

        #pragma unroll 1
        for (int c = 0; c < NCH; c++) {
            const int gc = t * NCH + c;
            const int s = gc & 1;
            if (gc + 1 < total_ch) cp_wait<1>(); else cp_wait<0>();
            __syncthreads();

            const char* stA = smdyn + s * STAGE;
            const char* stB = stA + 5120;
            #pragma unroll
            for (int kk = 0; kk < 4; kk++) {
                const int cb = kk * 64 + tig * 8;
                float2 fa0 = *reinterpret_cast<const float2*>(stA + soff(ar0, cb));
                float2 fa1 = *reinterpret_cast<const float2*>(stA + soff(ar1, cb));
                float2 fa2 = *reinterpret_cast<const float2*>(stA + soff(ar0, cb + 32));
                float2 fa3 = *reinterpret_cast<const float2*>(stA + soff(ar1, cb + 32));
                if (wid < 2) {   // q-norms: wid0 rows 0..15, wid1 rows 16..19
                    qn2a += fa0.x * fa0.x + fa0.y * fa0.y + fa2.x * fa2.x + fa2.y * fa2.y;
                    qn2b += fa1.x * fa1.x + fa1.y * fa1.y + fa3.x * fa3.x + fa3.y * fa3.y;
                }
                const uint32_t A0 = bfpack(fa0.x, fa0.y), A1 = bfpack(fa1.x, fa1.y);
                const uint32_t A2 = bfpack(fa2.x, fa2.y), A3 = bfpack(fa3.x, fa3.y);
                #pragma unroll
                for (int j = 0; j < 4; j++) {
                    int brow = n0 + 8 * j + g;
                    float2 fb0 = *reinterpret_cast<const float2*>(stB + soff(brow, cb));
                    float2 fb1 = *reinterpret_cast<const float2*>(stB + soff(brow, cb + 32));
                    if (mi == 0)
                        dn2[j] += fb0.x * fb0.x + fb0.y * fb0.y
                                + fb1.x * fb1.x + fb1.y * fb1.y;
                    mma16816(acc[j], A0, A1, A2, A3,
                             bfpack(fb0.x, fb0.y), bfpack(fb1.x, fb1.y));
                }
            }
            __syncthreads();
            if (gc + 2 < total_ch) issue_gc(gc + 2);   // crosses tile boundary
        }

        // ---- per-tile epilogue (next tile's chunks already in flight) ----
        if (mi == 0) {
            #pragma unroll
            for (int j = 0; j < 4; j++) {
                float v = dn2[j];
                v += __shfl_xor_sync(0xffffffffu, v, 1);
                v += __shfl_xor_sync(0xffffffffu, v, 2);
                if (tig == 0) sDn[n0 + 8 * j + g] = sqrtf(v);
            }
        }
        if (wid == 0) {
            float va = qn2a, vb = qn2b;
            va += __shfl_xor_sync(0xffffffffu, va, 1);
            va += __shfl_xor_sync(0xffffffffu, va, 2);
            vb += __shfl_xor_sync(0xffffffffu, vb, 1);
            vb += __shfl_xor_sync(0xffffffffu, vb, 2);
            if (tig == 0) { sQn[g] = sqrtf(va); sQn[g + 8] = sqrtf(vb); }
        }
        if (wid == 1) {
            float va = qn2a;
            va += __shfl_xor_sync(0xffffffffu, va, 1);
            va += __shfl_xor_sync(0xffffffffu, va, 2);
            if (tig == 0 && g < QL - 16) sQn[16 + g] = sqrtf(va);
        }
        if (tid < NB) sHist[tid] = 0;
        __syncthreads();

        {
            const int row0 = 16 * mi + g, row1 = row0 + 8;
            const int lc = tig * 2;
            const float qn0 = (row0 < QL) ? sQn[row0] : 1.f;
            const float qn1 = (row1 < QL) ? sQn[row1] : 1.f;
            #pragma unroll
            for (int j = 0; j < 4; j++) {
                const int col = n0 + 8 * j + lc;
                const float dn0 = sDn[col], dn1 = sDn[col + 1];
                #pragma unroll
                for (int e = 0; e < 4; e++) {
                    const int rw  = (e < 2) ? row0 : row1;
                    const float qn = (e < 2) ? qn0 : qn1;
                    const int cl  = col + (e & 1);
                    const float dn = (e & 1) ? dn1 : dn0;
                    int idx = -1;
                    if (rw < QL && dstart + cl < DL) {
                        float sim = acc[j][e] / fmaxf(qn * dn, EPSF);
                        float tt = (sim + 1.0f) * 5.5f;
                        int bi = (int)floorf(tt);
                        if (bi >= 0 && bi < NB) idx = bi;
                    }
                    unsigned m = __match_any_sync(0xffffffffu, idx);
                    if (idx >= 0 && lane == (__ffs(m) - 1))
                        atomicAdd(&sHist[idx], __popc(m));
                }
            }
        }
        __syncthreads();
        if (tid < NB) g_hist[idt * NB + tid] = sHist[tid];
        __threadfence();
        __syncthreads();
        if (tid == 0) atomicAdd(&g_arrive, 1);
    }
}

extern "C" void kernel_launch(void* const* d_in, const int* in_sizes, int n_in,
                              void* d_out, int out_size) {
    const float* hs     = (const float*)d_in[0];
    const float* W_hist = (const float*)d_in[1];
    const float* b_hist = (const float*)d_in[2];
    const float* W_comb = (const float*)d_in[3];
    const float* b_comb = (const float*)d_in[4];
    float* out = (float*)d_out;

    static bool attr_set = false;
    if (!attr_set) {
        cudaFuncSetAttribute(cedr_fused_kernel,
                             cudaFuncAttributeMaxDynamicSharedMemorySize, SM_SZ);
        attr_set = true;
    }
    cedr_fused_kernel<<<NWKR + 1, THR, SM_SZ>>>(hs, W_hist, b_hist, W_comb,
                                                b_comb, out);
}

// round 15
// speedup vs baseline: 1.3177x; 1.3177x over previous
#include <cuda_runtime.h>
#include <cuda_bf16.h>
#include <math.h>
#include <stdint.h>

#define L_    13
#define B_    16
#define S_    512
#define H_    768
#define QL    20
#define DL    492
#define NB    11
#define HID   5
#define NALL  14
#define KC    64            // K floats per chunk (256B/row fp32)
#define NCH   12            // 768 / 64
#define NDCH  4
#define EPSF  1e-8f
#define THR   256
#define NWORK (L_ * B_ * NDCH)   // 832

__device__ int g_hist[NWORK * NB];
__device__ int g_arrive = 0;

// stage: Q 24x256B (6144, rows 20-23 zero pad) + D 128x256B (32768) = 38912
#define STAGE 38912
#define SM_DN 77824          // 128 floats
#define SM_QN 78336          // 20 floats
#define SM_HI 78416          // 11 ints
#define SM_SZ 78464

extern __shared__ char smdyn[];

// 32B-granule XOR swizzle within a 256B row
__device__ __forceinline__ int swr(int row) { return (row & 7) ^ ((row >> 3) & 1); }
__device__ __forceinline__ uint32_t soff(int row, int col) {
    return (uint32_t)(row * 256 + ((((col >> 5) ^ swr(row)) << 5) | (col & 31)));
}

__device__ __forceinline__ uint32_t bfpack(float lo, float hi) {
    uint32_t r;
    asm("cvt.rn.bf16x2.f32 %0, %1, %2;" : "=r"(r) : "f"(hi), "f"(lo));
    return r;
}
__device__ __forceinline__ void cp16(void* dst, const void* src, bool pred) {
    unsigned s = (unsigned)__cvta_generic_to_shared(dst);
    int n = pred ? 16 : 0;
    asm volatile("cp.async.cg.shared.global [%0], [%1], 16, %2;"
                 :: "r"(s), "l"(src), "r"(n));
}
__device__ __forceinline__ void cp_commit() {
    asm volatile("cp.async.commit_group;");
}
template <int N>
__device__ __forceinline__ void cp_wait() {
    asm volatile("cp.async.wait_group %0;" :: "n"(N));
}
__device__ __forceinline__ void mma16816(float* c, uint32_t a0, uint32_t a1,
                                         uint32_t a2, uint32_t a3,
                                         uint32_t b0, uint32_t b1) {
    asm volatile(
        "mma.sync.aligned.m16n8k16.row.col.f32.bf16.bf16.f32 "
        "{%0,%1,%2,%3}, {%4,%5,%6,%7}, {%8,%9}, {%0,%1,%2,%3};"
        : "+f"(c[0]), "+f"(c[1]), "+f"(c[2]), "+f"(c[3])
        : "r"(a0), "r"(a1), "r"(a2), "r"(a3), "r"(b0), "r"(b1));
}

__global__ __launch_bounds__(THR)
void cedr_fused_kernel(const float* __restrict__ hs,
                       const float* __restrict__ W_hist,
                       const float* __restrict__ b_hist,
                       const float* __restrict__ W_comb,
                       const float* __restrict__ b_comb,
                       float* __restrict__ out) {
    const int tid  = threadIdx.x;
    const int lane = tid & 31;
    const int wid  = tid >> 5;

    // ======================= FINALIZER CTA =======================
    if (blockIdx.x == NWORK) {
        if (tid == 0) {
            while (atomicCAS(&g_arrive, NWORK, 0) != NWORK) {}
            __threadfence();
        }
        __syncthreads();
        const float inv_n = 1.0f / (float)(QL * DL);
        for (int b = wid; b < B_; b += 8) {
            float sum = 0.f;
            const float* cls = hs + (size_t)(12 * B_ + b) * S_ * H_;
            for (int h = lane; h < H_; h += 32) sum += cls[h] * W_comb[h];
            for (int i = lane; i < NALL * NB; i += 32) {
                int lp = i / NB, n = i % NB;
                int lsrc = (lp == 0) ? 0 : lp - 1;
                int cnt = 0;
                #pragma unroll
                for (int d = 0; d < NDCH; d++)
                    cnt += g_hist[(((lsrc * B_ + b) << 2) + d) * NB + n];
                float coef = 0.f;
                #pragma unroll
                for (int o = 0; o < HID; o++)
                    coef += W_hist[o * NB + n] * W_comb[H_ + lp * HID + o];
                sum += (float)cnt * inv_n * coef;
            }
            if (lane == 0) {
                float cst = b_comb[0];
                for (int lp = 0; lp < NALL; lp++)
                    #pragma unroll
                    for (int o = 0; o < HID; o++)
                        cst += b_hist[o] * W_comb[H_ + lp * HID + o];
                sum += cst;
            }
            #pragma unroll
            for (int o = 16; o > 0; o >>= 1)
                sum += __shfl_xor_sync(0xffffffffu, sum, o);
            if (lane == 0) out[b] = sum;
        }
        return;
    }

    // ======================= WORKER CTA =======================
    const int id = blockIdx.x;
    const int dc = id & 3, b = (id >> 2) & 15, l = id >> 6;
    const int dstart = dc * 128;
    float* sDn = reinterpret_cast<float*>(smdyn + SM_DN);
    float* sQn = reinterpret_cast<float*>(smdyn + SM_QN);
    int*   sHist = reinterpret_cast<int*>(smdyn + SM_HI);

    if (tid < NB) sHist[tid] = 0;

    // zero the Q-pad rows 20..23 of both stages (read as N-cols 20..23, discarded)
    if (tid < 128) {
        int s = tid >> 6, idx = tid & 63;
        int row = 20 + (idx >> 4), c16z = idx & 15;
        *reinterpret_cast<float4*>(smdyn + s * STAGE + soff(row, c16z * 16)) =
            make_float4(0.f, 0.f, 0.f, 0.f);
    }

    // staging roles (identical to champion): 16 lanes cover a 256B row
    const int c16 = lane & 15;
    const int lane_hi = lane >> 4;
    const int rbase = wid * 16 + lane_hi * 8;
    const float* dbase0 = hs + ((size_t)(l * B_ + b) * S_ + QL) * H_;
    const float* qbase  = hs + (size_t)(l * B_ + b) * S_ * H_;

    auto issue_chunk = [&](int c, int s) {
        char* stA = smdyn + s * STAGE;          // Q tile (24 rows)
        char* stB = stA + 6144;                 // D tile (128 rows)
        #pragma unroll
        for (int j = 0; j < 8; j++) {
            int row = rbase + j;
            int dgl = dstart + row;
            cp16(stB + soff(row, c16 * 16),
                 dbase0 + (size_t)dgl * H_ + c * KC + c16 * 4, dgl < DL);
        }
        {   // Q rows 0..15
            int qr = tid >> 4, qc = tid & 15;
            cp16(stA + soff(qr, qc * 16),
                 qbase + (size_t)qr * H_ + c * KC + qc * 4, true);
        }
        if (tid < 64) {  // Q rows 16..19
            int qr = 16 + (tid >> 4), qc = tid & 15;
            cp16(stA + soff(qr, qc * 16),
                 qbase + (size_t)qr * H_ + c * KC + qc * 4, true);
        }
        cp_commit();
    };

    // MMA geometry: A = D (M=128: warp m16 at 16*wid), B = Q (N=24: 3 n8 tiles)
    const int g = lane >> 2, tig = lane & 3;
    const int ar0 = 16 * wid + g, ar1 = ar0 + 8;

    float acc[3][4];
    #pragma unroll
    for (int j = 0; j < 3; j++)
        #pragma unroll
        for (int k = 0; k < 4; k++) acc[j][k] = 0.f;
    float dn2a = 0.f, dn2b = 0.f;
    float qn2[3] = {0.f, 0.f, 0.f};

    issue_chunk(0, 0);
    issue_chunk(1, 1);

    #pragma unroll 1
    for (int c = 0; c < NCH; c++) {
        const int s = c & 1;
        if (c + 1 < NCH) cp_wait<1>(); else cp_wait<0>();
        __syncthreads();

        const char* stA = smdyn + s * STAGE;
        const char* stB = stA + 6144;
        #pragma unroll
        for (int kk = 0; kk < 4; kk++) {
            const int cb = kk * 64 + tig * 8;
            // A fragments: D rows ar0/ar1 (each element touched by exactly 1 warp)
            float2 fa0 = *reinterpret_cast<const float2*>(stB + soff(ar0, cb));
            float2 fa1 = *reinterpret_cast<const float2*>(stB + soff(ar1, cb));
            float2 fa2 = *reinterpret_cast<const float2*>(stB + soff(ar0, cb + 32));
            float2 fa3 = *reinterpret_cast<const float2*>(stB + soff(ar1, cb + 32));
            dn2a += fa0.x * fa0.x + fa0.y * fa0.y + fa2.x * fa2.x + fa2.y * fa2.y;
            dn2b += fa1.x * fa1.x + fa1.y * fa1.y + fa3.x * fa3.x + fa3.y * fa3.y;
            const uint32_t A0 = bfpack(fa0.x, fa0.y), A1 = bfpack(fa1.x, fa1.y);
            const uint32_t A2 = bfpack(fa2.x, fa2.y), A3 = bfpack(fa3.x, fa3.y);
            #pragma unroll
            for (int j = 0; j < 3; j++) {
                int qrow = 8 * j + g;           // Q row (n index)
                float2 fq0 = *reinterpret_cast<const float2*>(stA + soff(qrow, cb));
                float2 fq1 = *reinterpret_cast<const float2*>(stA + soff(qrow, cb + 32));
                qn2[j] += fq0.x * fq0.x + fq0.y * fq0.y
                        + fq1.x * fq1.x + fq1.y * fq1.y;
                mma16816(acc[j], A0, A1, A2, A3,
                         bfpack(fq0.x, fq0.y), bfpack(fq1.x, fq1.y));
            }
        }
        __syncthreads();
        if (c + 2 < NCH) issue_chunk(c + 2, s);
    }

    // ---- norms -> smem ----
    {   // d-norms: every warp owns rows ar0/ar1; reduce over tig (quad)
        float va = dn2a, vb = dn2b;
        va += __shfl_xor_sync(0xffffffffu, va, 1);
        va += __shfl_xor_sync(0xffffffffu, va, 2);
        vb += __shfl_xor_sync(0xffffffffu, vb, 1);
        vb += __shfl_xor_sync(0xffffffffu, vb, 2);
        if (tig == 0) { sDn[ar0] = sqrtf(va); sDn[ar1] = sqrtf(vb); }
    }
    if (wid == 0) {   // q-norms (identical in all warps; warp 0 writes)
        #pragma unroll
        for (int j = 0; j < 3; j++) {
            float v = qn2[j];
            v += __shfl_xor_sync(0xffffffffu, v, 1);
            v += __shfl_xor_sync(0xffffffffu, v, 2);
            int qr = 8 * j + g;
            if (tig == 0 && qr < QL) sQn[qr] = sqrtf(v);
        }
    }
    __syncthreads();

    // ---- epilogue: cosine -> bin -> warp-aggregated histogram ----
    {
        const float dnr0 = sDn[ar0], dnr1 = sDn[ar1];
        #pragma unroll
        for (int j = 0; j < 3; j++) {
            const int qc0 = 8 * j + tig * 2;
            #pragma unroll
            for (int e = 0; e < 4; e++) {
                const int dl  = (e < 2) ? ar0 : ar1;
                const float dn = (e < 2) ? dnr0 : dnr1;
                const int qc  = qc0 + (e & 1);
                int idx = -1;
                if (qc < QL && dstart + dl < DL) {
                    float sim = acc[j][e] / fmaxf(sQn[qc] * dn, EPSF);
                    float t = (sim + 1.0f) * 5.5f;
                    int bi = (int)floorf(t);
                    if (bi >= 0 && bi < NB) idx = bi;
                }
                unsigned m = __match_any_sync(0xffffffffu, idx);
                if (idx >= 0 && lane == (__ffs(m) - 1))
                    atomicAdd(&sHist[idx], __popc(m));
            }
        }
    }
    __syncthreads();
    if (tid < NB)
        g_hist[id * NB + tid] = sHist[tid];
    __threadfence();
    __syncthreads();
    if (tid == 0) atomicAdd(&g_arrive, 1);
}

extern "C" void kernel_launch(void* const* d_in, const int* in_sizes, int n_in,
                              void* d_out, int out_size) {
    const float* hs     = (const float*)d_in[0];
    const float* W_hist = (const float*)d_in[1];
    const float* b_hist = (const float*)d_in[2];
    const float* W_comb = (const float*)d_in[3];
    const float* b_comb = (const float*)d_in[4];
    float* out = (float*)d_out;

    static bool attr_set = false;
    if (!attr_set) {
        cudaFuncSetAttribute(cedr_fused_kernel,
                             cudaFuncAttributeMaxDynamicSharedMemorySize, SM_SZ);
        attr_set = true;
    }
    cedr_fused_kernel<<<NWORK + 1, THR, SM_SZ>>>(hs, W_hist, b_hist, W_comb,
                                                 b_comb, out);
}

// round 16
// speedup vs baseline: 1.3488x; 1.0236x over previous
#include <cuda_runtime.h>
#include <cuda_bf16.h>
#include <math.h>
#include <stdint.h>

#define L_    13
#define B_    16
#define S_    512
#define H_    768
#define QL    20
#define DL    492
#define NB    11
#define HID   5
#define NALL  14
#define KC    64            // K floats per chunk (256B/row fp32)
#define NCH   12            // 768 / 64
#define NDCH  4
#define EPSF  1e-8f
#define THR   256
#define NWORK (L_ * B_ * NDCH)   // 832

__device__ int g_hist[NWORK * NB];
__device__ int g_arrive = 0;

// stage: Q 24x256B (rows 20-23 zero pad) + D 128x256B = 38912; 2 stages.
// Tail data (sDn/sQn/sHist) lives INSIDE stage 0 after the loop (dead space),
// keeping SM_SZ at exactly 2*STAGE = 77824 -> 3 CTAs per SM (3*77824 = 233472).
#define STAGE 38912
#define SM_DN 0              // 128 floats  (stage-0 offset, post-loop only)
#define SM_QN 512            // 20 floats
#define SM_HI 592            // 11 ints
#define SM_SZ (2 * STAGE)

extern __shared__ char smdyn[];

// 32B-granule XOR swizzle within a 256B row
__device__ __forceinline__ int swr(int row) { return (row & 7) ^ ((row >> 3) & 1); }
__device__ __forceinline__ uint32_t soff(int row, int col) {
    return (uint32_t)(row * 256 + ((((col >> 5) ^ swr(row)) << 5) | (col & 31)));
}

__device__ __forceinline__ uint32_t bfpack(float lo, float hi) {
    uint32_t r;
    asm("cvt.rn.bf16x2.f32 %0, %1, %2;" : "=r"(r) : "f"(hi), "f"(lo));
    return r;
}
__device__ __forceinline__ void cp16(void* dst, const void* src, bool pred) {
    unsigned s = (unsigned)__cvta_generic_to_shared(dst);
    int n = pred ? 16 : 0;
    asm volatile("cp.async.cg.shared.global [%0], [%1], 16, %2;"
                 :: "r"(s), "l"(src), "r"(n));
}
__device__ __forceinline__ void cp_commit() {
    asm volatile("cp.async.commit_group;");
}
template <int N>
__device__ __forceinline__ void cp_wait() {
    asm volatile("cp.async.wait_group %0;" :: "n"(N));
}
__device__ __forceinline__ void mma16816(float* c, uint32_t a0, uint32_t a1,
                                         uint32_t a2, uint32_t a3,
                                         uint32_t b0, uint32_t b1) {
    asm volatile(
        "mma.sync.aligned.m16n8k16.row.col.f32.bf16.bf16.f32 "
        "{%0,%1,%2,%3}, {%4,%5,%6,%7}, {%8,%9}, {%0,%1,%2,%3};"
        : "+f"(c[0]), "+f"(c[1]), "+f"(c[2]), "+f"(c[3])
        : "r"(a0), "r"(a1), "r"(a2), "r"(a3), "r"(b0), "r"(b1));
}

__global__ __launch_bounds__(THR, 3)
void cedr_fused_kernel(const float* __restrict__ hs,
                       const float* __restrict__ W_hist,
                       const float* __restrict__ b_hist,
                       const float* __restrict__ W_comb,
                       const float* __restrict__ b_comb,
                       float* __restrict__ out) {
    const int tid  = threadIdx.x;
    const int lane = tid & 31;
    const int wid  = tid >> 5;

    // ======================= FINALIZER CTA =======================
    if (blockIdx.x == NWORK) {
        if (tid == 0) {
            while (atomicCAS(&g_arrive, NWORK, 0) != NWORK) {}
            __threadfence();
        }
        __syncthreads();
        const float inv_n = 1.0f / (float)(QL * DL);
        for (int b = wid; b < B_; b += 8) {
            float sum = 0.f;
            const float* cls = hs + (size_t)(12 * B_ + b) * S_ * H_;
            for (int h = lane; h < H_; h += 32) sum += cls[h] * W_comb[h];
            for (int i = lane; i < NALL * NB; i += 32) {
                int lp = i / NB, n = i % NB;
                int lsrc = (lp == 0) ? 0 : lp - 1;
                int cnt = 0;
                #pragma unroll
                for (int d = 0; d < NDCH; d++)
                    cnt += g_hist[(((lsrc * B_ + b) << 2) + d) * NB + n];
                float coef = 0.f;
                #pragma unroll
                for (int o = 0; o < HID; o++)
                    coef += W_hist[o * NB + n] * W_comb[H_ + lp * HID + o];
                sum += (float)cnt * inv_n * coef;
            }
            if (lane == 0) {
                float cst = b_comb[0];
                for (int lp = 0; lp < NALL; lp++)
                    #pragma unroll
                    for (int o = 0; o < HID; o++)
                        cst += b_hist[o] * W_comb[H_ + lp * HID + o];
                sum += cst;
            }
            #pragma unroll
            for (int o = 16; o > 0; o >>= 1)
                sum += __shfl_xor_sync(0xffffffffu, sum, o);
            if (lane == 0) out[b] = sum;
        }
        return;
    }

    // ======================= WORKER CTA =======================
    const int id = blockIdx.x;
    const int dc = id & 3, b = (id >> 2) & 15, l = id >> 6;
    const int dstart = dc * 128;
    float* sDn = reinterpret_cast<float*>(smdyn + SM_DN);
    float* sQn = reinterpret_cast<float*>(smdyn + SM_QN);
    int*   sHist = reinterpret_cast<int*>(smdyn + SM_HI);

    // zero the Q-pad rows 20..23 of both stages (cp.async never touches them;
    // they read back as N-cols 20..23, whose outputs are discarded)
    if (tid < 128) {
        int s = tid >> 6, idx = tid & 63;
        int row = 20 + (idx >> 4), c16z = idx & 15;
        *reinterpret_cast<float4*>(smdyn + s * STAGE + soff(row, c16z * 16)) =
            make_float4(0.f, 0.f, 0.f, 0.f);
    }

    // staging roles: 16 lanes cover a 256B row
    const int c16 = lane & 15;
    const int lane_hi = lane >> 4;
    const int rbase = wid * 16 + lane_hi * 8;
    const float* dbase0 = hs + ((size_t)(l * B_ + b) * S_ + QL) * H_;
    const float* qbase  = hs + (size_t)(l * B_ + b) * S_ * H_;

    auto issue_chunk = [&](int c, int s) {
        char* stA = smdyn + s * STAGE;          // Q tile (24 rows)
        char* stB = stA + 6144;                 // D tile (128 rows)
        #pragma unroll
        for (int j = 0; j < 8; j++) {
            int row = rbase + j;
            int dgl = dstart + row;
            cp16(stB + soff(row, c16 * 16),
                 dbase0 + (size_t)dgl * H_ + c * KC + c16 * 4, dgl < DL);
        }
        {   // Q rows 0..15
            int qr = tid >> 4, qc = tid & 15;
            cp16(stA + soff(qr, qc * 16),
                 qbase + (size_t)qr * H_ + c * KC + qc * 4, true);
        }
        if (tid < 64) {  // Q rows 16..19
            int qr = 16 + (tid >> 4), qc = tid & 15;
            cp16(stA + soff(qr, qc * 16),
                 qbase + (size_t)qr * H_ + c * KC + qc * 4, true);
        }
        cp_commit();
    };

    // MMA geometry: A = D (M=128: warp m16 at 16*wid), B = Q (N=24: 3 n8 tiles)
    const int g = lane >> 2, tig = lane & 3;
    const int ar0 = 16 * wid + g, ar1 = ar0 + 8;

    float acc[3][4];
    #pragma unroll
    for (int j = 0; j < 3; j++)
        #pragma unroll
        for (int k = 0; k < 4; k++) acc[j][k] = 0.f;
    float dn2a = 0.f, dn2b = 0.f;
    float qn2[3] = {0.f, 0.f, 0.f};

    issue_chunk(0, 0);
    issue_chunk(1, 1);

    #pragma unroll 1
    for (int c = 0; c < NCH; c++) {
        const int s = c & 1;
        if (c + 1 < NCH) cp_wait<1>(); else cp_wait<0>();
        __syncthreads();

        const char* stA = smdyn + s * STAGE;
        const char* stB = stA + 6144;
        #pragma unroll
        for (int kk = 0; kk < 4; kk++) {
            const int cb = kk * 64 + tig * 8;
            float2 fa0 = *reinterpret_cast<const float2*>(stB + soff(ar0, cb));
            float2 fa1 = *reinterpret_cast<const float2*>(stB + soff(ar1, cb));
            float2 fa2 = *reinterpret_cast<const float2*>(stB + soff(ar0, cb + 32));
            float2 fa3 = *reinterpret_cast<const float2*>(stB + soff(ar1, cb + 32));
            dn2a += fa0.x * fa0.x + fa0.y * fa0.y + fa2.x * fa2.x + fa2.y * fa2.y;
            dn2b += fa1.x * fa1.x + fa1.y * fa1.y + fa3.x * fa3.x + fa3.y * fa3.y;
            const uint32_t A0 = bfpack(fa0.x, fa0.y), A1 = bfpack(fa1.x, fa1.y);
            const uint32_t A2 = bfpack(fa2.x, fa2.y), A3 = bfpack(fa3.x, fa3.y);
            #pragma unroll
            for (int j = 0; j < 3; j++) {
                int qrow = 8 * j + g;
                float2 fq0 = *reinterpret_cast<const float2*>(stA + soff(qrow, cb));
                float2 fq1 = *reinterpret_cast<const float2*>(stA + soff(qrow, cb + 32));
                qn2[j] += fq0.x * fq0.x + fq0.y * fq0.y
                        + fq1.x * fq1.x + fq1.y * fq1.y;
                mma16816(acc[j], A0, A1, A2, A3,
                         bfpack(fq0.x, fq0.y), bfpack(fq1.x, fq1.y));
            }
        }
        __syncthreads();
        if (c + 2 < NCH) issue_chunk(c + 2, s);
    }
    // stage 0 is dead now (chunk 10 fully consumed before the c=11 barrier);
    // its first 640 bytes become sDn/sQn/sHist.

    // ---- norms -> smem ----
    {
        float va = dn2a, vb = dn2b;
        va += __shfl_xor_sync(0xffffffffu, va, 1);
        va += __shfl_xor_sync(0xffffffffu, va, 2);
        vb += __shfl_xor_sync(0xffffffffu, vb, 1);
        vb += __shfl_xor_sync(0xffffffffu, vb, 2);
        if (tig == 0) { sDn[ar0] = sqrtf(va); sDn[ar1] = sqrtf(vb); }
    }
    if (wid == 0) {
        #pragma unroll
        for (int j = 0; j < 3; j++) {
            float v = qn2[j];
            v += __shfl_xor_sync(0xffffffffu, v, 1);
            v += __shfl_xor_sync(0xffffffffu, v, 2);
            int qr = 8 * j + g;
            if (tig == 0 && qr < QL) sQn[qr] = sqrtf(v);
        }
    }
    if (wid == 1 && lane < NB) sHist[lane] = 0;
    __syncthreads();

    // ---- epilogue: cosine -> bin -> warp-aggregated histogram ----
    {
        const float dnr0 = sDn[ar0], dnr1 = sDn[ar1];
        #pragma unroll
        for (int j = 0; j < 3; j++) {
            const int qc0 = 8 * j + tig * 2;
            #pragma unroll
            for (int e = 0; e < 4; e++) {
                const int dl  = (e < 2) ? ar0 : ar1;
                const float dn = (e < 2) ? dnr0 : dnr1;
                const int qc  = qc0 + (e & 1);
                int idx = -1;
                if (qc < QL && dstart + dl < DL) {
                    float sim = acc[j][e] / fmaxf(sQn[qc] * dn, EPSF);
                    float t = (sim + 1.0f) * 5.5f;
                    int bi = (int)floorf(t);
                    if (bi >= 0 && bi < NB) idx = bi;
                }
                unsigned m = __match_any_sync(0xffffffffu, idx);
                if (idx >= 0 && lane == (__ffs(m) - 1))
                    atomicAdd(&sHist[idx], __popc(m));
            }
        }
    }
    __syncthreads();
    if (tid < NB)
        g_hist[id * NB + tid] = sHist[tid];
    __threadfence();
    __syncthreads();
    if (tid == 0) atomicAdd(&g_arrive, 1);
}

extern "C" void kernel_launch(void* const* d_in, const int* in_sizes, int n_in,
                              void* d_out, int out_size) {
    const float* hs     = (const float*)d_in[0];
    const float* W_hist = (const float*)d_in[1];
    const float* b_hist = (const float*)d_in[2];
    const float* W_comb = (const float*)d_in[3];
    const float* b_comb = (const float*)d_in[4];
    float* out = (float*)d_out;

    static bool attr_set = false;
    if (!attr_set) {
        cudaFuncSetAttribute(cedr_fused_kernel,
                             cudaFuncAttributeMaxDynamicSharedMemorySize, SM_SZ);
        attr_set = true;
    }
    cedr_fused_kernel<<<NWORK + 1, THR, SM_SZ>>>(hs, W_hist, b_hist, W_comb,
                                                 b_comb, out);
}

// round 17
// speedup vs baseline: 1.4255x; 1.0569x over previous
#include <cuda_runtime.h>
#include <cuda_bf16.h>
#include <math.h>
#include <stdint.h>

#define L_    13
#define B_    16
#define S_    512
#define H_    768
#define QL    20
#define DL    492
#define NB    11
#define HID   5
#define NALL  14
#define KC    64            // K floats per chunk (256B/row fp32)
#define NCH   12            // 768 / 64
#define NDCH  4
#define EPSF  1e-8f
#define THR   256
#define NWORK (L_ * B_ * NDCH)   // 832

__device__ int g_hist[NWORK * NB];
__device__ int g_arrive = 0;

// stage: Q 20x256B (5120) + D 128x256B (32768) = 37888; 2 stages = 75776.
// 3 CTAs/SM: 3*(75776 + 1024 reserved) = 230400 <= 233472 (228KB).
// Tail (sDn/sQn/sHist) lives inside stage 0 after the loop (dead space).
#define STAGE 37888
#define SM_DN 0              // 128 floats (stage-0 offset, post-loop only)
#define SM_QN 512            // 20 floats
#define SM_HI 592            // 11 ints
#define SM_SZ (2 * STAGE)

extern __shared__ char smdyn[];

// 32B-granule XOR swizzle within a 256B row
__device__ __forceinline__ int swr(int row) { return (row & 7) ^ ((row >> 3) & 1); }
__device__ __forceinline__ uint32_t soff(int row, int col) {
    return (uint32_t)(row * 256 + ((((col >> 5) ^ swr(row)) << 5) | (col & 31)));
}

__device__ __forceinline__ uint32_t bfpack(float lo, float hi) {
    uint32_t r;
    asm("cvt.rn.bf16x2.f32 %0, %1, %2;" : "=r"(r) : "f"(hi), "f"(lo));
    return r;
}
__device__ __forceinline__ void cp16(void* dst, const void* src, bool pred) {
    unsigned s = (unsigned)__cvta_generic_to_shared(dst);
    int n = pred ? 16 : 0;
    asm volatile("cp.async.cg.shared.global [%0], [%1], 16, %2;"
                 :: "r"(s), "l"(src), "r"(n));
}
__device__ __forceinline__ void cp_commit() {
    asm volatile("cp.async.commit_group;");
}
template <int N>
__device__ __forceinline__ void cp_wait() {
    asm volatile("cp.async.wait_group %0;" :: "n"(N));
}
__device__ __forceinline__ void mma16816(float* c, uint32_t a0, uint32_t a1,
                                         uint32_t a2, uint32_t a3,
                                         uint32_t b0, uint32_t b1) {
    asm volatile(
        "mma.sync.aligned.m16n8k16.row.col.f32.bf16.bf16.f32 "
        "{%0,%1,%2,%3}, {%4,%5,%6,%7}, {%8,%9}, {%0,%1,%2,%3};"
        : "+f"(c[0]), "+f"(c[1]), "+f"(c[2]), "+f"(c[3])
        : "r"(a0), "r"(a1), "r"(a2), "r"(a3), "r"(b0), "r"(b1));
}

__global__ __launch_bounds__(THR, 3)
void cedr_fused_kernel(const float* __restrict__ hs,
                       const float* __restrict__ W_hist,
                       const float* __restrict__ b_hist,
                       const float* __restrict__ W_comb,
                       const float* __restrict__ b_comb,
                       float* __restrict__ out) {
    const int tid  = threadIdx.x;
    const int lane = tid & 31;
    const int wid  = tid >> 5;

    // ======================= FINALIZER CTA =======================
    if (blockIdx.x == NWORK) {
        if (tid == 0) {
            while (atomicCAS(&g_arrive, NWORK, 0) != NWORK) {}
            __threadfence();
        }
        __syncthreads();
        const float inv_n = 1.0f / (float)(QL * DL);
        for (int b = wid; b < B_; b += 8) {
            float sum = 0.f;
            const float* cls = hs + (size_t)(12 * B_ + b) * S_ * H_;
            for (int h = lane; h < H_; h += 32) sum += cls[h] * W_comb[h];
            for (int i = lane; i < NALL * NB; i += 32) {
                int lp = i / NB, n = i % NB;
                int lsrc = (lp == 0) ? 0 : lp - 1;
                int cnt = 0;
                #pragma unroll
                for (int d = 0; d < NDCH; d++)
                    cnt += g_hist[(((lsrc * B_ + b) << 2) + d) * NB + n];
                float coef = 0.f;
                #pragma unroll
                for (int o = 0; o < HID; o++)
                    coef += W_hist[o * NB + n] * W_comb[H_ + lp * HID + o];
                sum += (float)cnt * inv_n * coef;
            }
            if (lane == 0) {
                float cst = b_comb[0];
                for (int lp = 0; lp < NALL; lp++)
                    #pragma unroll
                    for (int o = 0; o < HID; o++)
                        cst += b_hist[o] * W_comb[H_ + lp * HID + o];
                sum += cst;
            }
            #pragma unroll
            for (int o = 16; o > 0; o >>= 1)
                sum += __shfl_xor_sync(0xffffffffu, sum, o);
            if (lane == 0) out[b] = sum;
        }
        return;
    }

    // ======================= WORKER CTA =======================
    const int id = blockIdx.x;
    const int dc = id & 3, b = (id >> 2) & 15, l = id >> 6;
    const int dstart = dc * 128;
    float* sDn = reinterpret_cast<float*>(smdyn + SM_DN);
    float* sQn = reinterpret_cast<float*>(smdyn + SM_QN);
    int*   sHist = reinterpret_cast<int*>(smdyn + SM_HI);

    // staging roles: 16 lanes cover a 256B row
    const int c16 = lane & 15;
    const int lane_hi = lane >> 4;
    const int rbase = wid * 16 + lane_hi * 8;
    const float* dbase0 = hs + ((size_t)(l * B_ + b) * S_ + QL) * H_;
    const float* qbase  = hs + (size_t)(l * B_ + b) * S_ * H_;

    auto issue_chunk = [&](int c, int s) {
        char* stA = smdyn + s * STAGE;          // Q tile (20 rows)
        char* stB = stA + 5120;                 // D tile (128 rows)
        #pragma unroll
        for (int j = 0; j < 8; j++) {
            int row = rbase + j;
            int dgl = dstart + row;
            cp16(stB + soff(row, c16 * 16),
                 dbase0 + (size_t)dgl * H_ + c * KC + c16 * 4, dgl < DL);
        }
        {   // Q rows 0..15
            int qr = tid >> 4, qc = tid & 15;
            cp16(stA + soff(qr, qc * 16),
                 qbase + (size_t)qr * H_ + c * KC + qc * 4, true);
        }
        if (tid < 64) {  // Q rows 16..19
            int qr = 16 + (tid >> 4), qc = tid & 15;
            cp16(stA + soff(qr, qc * 16),
                 qbase + (size_t)qr * H_ + c * KC + qc * 4, true);
        }
        cp_commit();
    };

    // MMA geometry: A = D (M=128: warp m16 at 16*wid), B = Q (N=24: 3 n8 tiles)
    const int g = lane >> 2, tig = lane & 3;
    const int ar0 = 16 * wid + g, ar1 = ar0 + 8;
    // B-fragment load rows; j=2 lanes with g>=4 clamp to row 19 (their output
    // columns 20..23 are garbage and discarded in the epilogue).
    const int qrow_ld[3] = { g, 8 + g, (16 + g < QL) ? 16 + g : QL - 1 };

    float acc[3][4];
    #pragma unroll
    for (int j = 0; j < 3; j++)
        #pragma unroll
        for (int k = 0; k < 4; k++) acc[j][k] = 0.f;
    float dn2a = 0.f, dn2b = 0.f;
    float qn2[3] = {0.f, 0.f, 0.f};

    issue_chunk(0, 0);
    issue_chunk(1, 1);

    #pragma unroll 1
    for (int c = 0; c < NCH; c++) {
        const int s = c & 1;
        if (c + 1 < NCH) cp_wait<1>(); else cp_wait<0>();
        __syncthreads();

        const char* stA = smdyn + s * STAGE;
        const char* stB = stA + 5120;
        #pragma unroll
        for (int kk = 0; kk < 4; kk++) {
            const int cb = kk * 64 + tig * 8;
            float2 fa0 = *reinterpret_cast<const float2*>(stB + soff(ar0, cb));
            float2 fa1 = *reinterpret_cast<const float2*>(stB + soff(ar1, cb));
            float2 fa2 = *reinterpret_cast<const float2*>(stB + soff(ar0, cb + 32));
            float2 fa3 = *reinterpret_cast<const float2*>(stB + soff(ar1, cb + 32));
            dn2a += fa0.x * fa0.x + fa0.y * fa0.y + fa2.x * fa2.x + fa2.y * fa2.y;
            dn2b += fa1.x * fa1.x + fa1.y * fa1.y + fa3.x * fa3.x + fa3.y * fa3.y;
            const uint32_t A0 = bfpack(fa0.x, fa0.y), A1 = bfpack(fa1.x, fa1.y);
            const uint32_t A2 = bfpack(fa2.x, fa2.y), A3 = bfpack(fa3.x, fa3.y);
            #pragma unroll
            for (int j = 0; j < 3; j++) {
                int qrow = qrow_ld[j];
                float2 fq0 = *reinterpret_cast<const float2*>(stA + soff(qrow, cb));
                float2 fq1 = *reinterpret_cast<const float2*>(stA + soff(qrow, cb + 32));
                qn2[j] += fq0.x * fq0.x + fq0.y * fq0.y
                        + fq1.x * fq1.x + fq1.y * fq1.y;
                mma16816(acc[j], A0, A1, A2, A3,
                         bfpack(fq0.x, fq0.y), bfpack(fq1.x, fq1.y));
            }
        }
        __syncthreads();
        if (c + 2 < NCH) issue_chunk(c + 2, s);
    }
    // stage 0 is dead now; its first 640 bytes become sDn/sQn/sHist.

    // ---- norms -> smem ----
    {
        float va = dn2a, vb = dn2b;
        va += __shfl_xor_sync(0xffffffffu, va, 1);
        va += __shfl_xor_sync(0xffffffffu, va, 2);
        vb += __shfl_xor_sync(0xffffffffu, vb, 1);
        vb += __shfl_xor_sync(0xffffffffu, vb, 2);
        if (tig == 0) { sDn[ar0] = sqrtf(va); sDn[ar1] = sqrtf(vb); }
    }
    if (wid == 0) {
        #pragma unroll
        for (int j = 0; j < 3; j++) {
            float v = qn2[j];
            v += __shfl_xor_sync(0xffffffffu, v, 1);
            v += __shfl_xor_sync(0xffffffffu, v, 2);
            int qr = 8 * j + g;
            if (tig == 0 && qr < QL) sQn[qr] = sqrtf(v);
        }
    }
    if (wid == 1 && lane < NB) sHist[lane] = 0;
    __syncthreads();

    // ---- epilogue: cosine -> bin -> warp-aggregated histogram ----
    {
        const float dnr0 = sDn[ar0], dnr1 = sDn[ar1];
        #pragma unroll
        for (int j = 0; j < 3; j++) {
            const int qc0 = 8 * j + tig * 2;
            #pragma unroll
            for (int e = 0; e < 4; e++) {
                const int dl  = (e < 2) ? ar0 : ar1;
                const float dn = (e < 2) ? dnr0 : dnr1;
                const int qc  = qc0 + (e & 1);
                int idx = -1;
                if (qc < QL && dstart + dl < DL) {
                    float sim = acc[j][e] / fmaxf(sQn[qc] * dn, EPSF);
                    float t = (sim + 1.0f) * 5.5f;
                    int bi = (int)floorf(t);
                    if (bi >= 0 && bi < NB) idx = bi;
                }
                unsigned m = __match_any_sync(0xffffffffu, idx);
                if (idx >= 0 && lane == (__ffs(m) - 1))
                    atomicAdd(&sHist[idx], __popc(m));
            }
        }
    }
    __syncthreads();
    if (tid < NB)
        g_hist[id * NB + tid] = sHist[tid];
    __threadfence();
    __syncthreads();
    if (tid == 0) atomicAdd(&g_arrive, 1);
}

extern "C" void kernel_launch(void* const* d_in, const int* in_sizes, int n_in,
                              void* d_out, int out_size) {
    const float* hs     = (const float*)d_in[0];
    const float* W_hist = (const float*)d_in[1];
    const float* b_hist = (const float*)d_in[2];
    const float* W_comb = (const float*)d_in[3];
    const float* b_comb = (const float*)d_in[4];
    float* out = (float*)d_out;

    static bool attr_set = false;
    if (!attr_set) {
        cudaFuncSetAttribute(cedr_fused_kernel,
                             cudaFuncAttributeMaxDynamicSharedMemorySize, SM_SZ);
        attr_set = true;
    }
    cedr_fused_kernel<<<NWORK + 1, THR, SM_SZ>>>(hs, W_hist, b_hist, W_comb,
                                                 b_comb, out);
}